// round 8
// baseline (speedup 1.0000x reference)
#include <cuda_runtime.h>
#include <cuda_bf16.h>
#include <math.h>

#define N_NODES 100000
#define D_IN    64
#define D_H     32
#define TOTAL_H (N_NODES * D_H)
#define BM      128
#define XS      (BM + 4)

// ---------------- scratch (device globals, 16B aligned) ---------------------
__device__ __align__(16) float g_aggp[TOTAL_H];
__device__ __align__(16) float g_aggc[TOTAL_H];
__device__ __align__(16) float g_ycp [TOTAL_H];
__device__ __align__(16) float g_ypc [TOTAL_H];
__device__ __align__(16) float g_linc[TOTAL_H];
__device__ __align__(16) float g_linp[TOTAL_H];
__device__ __align__(16) float g_cntp[N_NODES];
__device__ __align__(16) float g_cntc[N_NODES];
__device__ __align__(16) float g_gc  [N_NODES];
__device__ __align__(16) float g_aggs[N_NODES];
__device__ float g_w2l_eff[D_H];
__device__ float g_w2r_eff[D_H];
__device__ float g_bias_eff[1];

// ---------------- kernels ---------------------------------------------------

__global__ void k_zero_all() {
    int i = blockIdx.x * blockDim.x + threadIdx.x;
    int stride = gridDim.x * blockDim.x;
    float4 z = make_float4(0.f, 0.f, 0.f, 0.f);
    for (int k = i; k < TOTAL_H / 4; k += stride) {
        reinterpret_cast<float4*>(g_aggp)[k] = z;
        reinterpret_cast<float4*>(g_aggc)[k] = z;
    }
    for (int k = i; k < N_NODES / 4; k += stride) {
        reinterpret_cast<float4*>(g_cntp)[k] = z;
        reinterpret_cast<float4*>(g_cntc)[k] = z;
        reinterpret_cast<float4*>(g_aggs)[k] = z;
    }
}

__global__ void k_eff(const float* __restrict__ W2l, const float* __restrict__ W2r,
                      const float* __restrict__ b2, const float* __restrict__ Wlin,
                      const float* __restrict__ blin) {
    int i = threadIdx.x;  // 0..31
    float wl = 0.f, wr = 0.f;
    #pragma unroll
    for (int j = 0; j < D_H; ++j) {
        float wj = Wlin[j];
        wl += W2l[i * D_H + j] * wj;
        wr += W2r[i * D_H + j] * wj;
    }
    g_w2l_eff[i] = wl;
    g_w2r_eff[i] = wr;
    float bv = b2[i] * Wlin[i];
    #pragma unroll
    for (int o = 16; o; o >>= 1) bv += __shfl_xor_sync(0xffffffffu, bv, o);
    if (i == 0) g_bias_eff[0] = bv + blin[0];
}

// Register-tiled GEMM: C[128 nodes][64 outs] = x_tile @ [Wl | Wr], K=64.
// cols 0..31 -> y, cols 32..63 -> lin (+bias).
// 256 threads; each computes 8 nodes x 4 outs. Per k: 3 LDS.128 + 32 FFMA.
__global__ void k_prep(const float* __restrict__ x,
                       const float* __restrict__ Wl, const float* __restrict__ Wr,
                       const float* __restrict__ b,
                       float* __restrict__ y, float* __restrict__ lin, int n) {
    __shared__ float sW[D_IN * 64];     // [k][out0..63] = [Wl | Wr]  (16KB)
    __shared__ float sX[D_IN * XS];     // [k][node], padded          (33.8KB)
    __shared__ float sb2[D_H];
    int tid = threadIdx.x;

    for (int i = tid; i < D_IN * 8; i += 256) {
        int k = i >> 3, q = i & 7;
        reinterpret_cast<float4*>(sW)[k * 16 + q]     = reinterpret_cast<const float4*>(Wl)[i];
        reinterpret_cast<float4*>(sW)[k * 16 + 8 + q] = reinterpret_cast<const float4*>(Wr)[i];
    }
    if (tid < D_H) sb2[tid] = b[tid];

    int base = blockIdx.x * BM;
    for (int i = tid; i < BM * 16; i += 256) {   // BM nodes * 16 float4
        int node = i >> 4;
        int q    = i & 15;
        int gn = base + node;
        float4 v = (gn < n) ? reinterpret_cast<const float4*>(x + (size_t)gn * D_IN)[q]
                            : make_float4(0.f, 0.f, 0.f, 0.f);
        int k4 = q * 4;
        sX[(k4 + 0) * XS + node] = v.x;
        sX[(k4 + 1) * XS + node] = v.y;
        sX[(k4 + 2) * XS + node] = v.z;
        sX[(k4 + 3) * XS + node] = v.w;
    }
    __syncthreads();

    int tn = tid & 15;        // output group: cols 4*tn .. 4*tn+3
    int tm = tid >> 4;        // node group:  rows 8*tm .. 8*tm+7 (0..15)
    int n0 = tn * 4, m0 = tm * 8;

    float acc[8][4];
    #pragma unroll
    for (int i = 0; i < 8; ++i)
        #pragma unroll
        for (int j = 0; j < 4; ++j) acc[i][j] = 0.f;

    #pragma unroll 4
    for (int k = 0; k < D_IN; ++k) {
        float4 w  = *reinterpret_cast<const float4*>(&sW[k * 64 + n0]);
        float4 xa = *reinterpret_cast<const float4*>(&sX[k * XS + m0]);
        float4 xb = *reinterpret_cast<const float4*>(&sX[k * XS + m0 + 4]);
        float xm[8] = {xa.x, xa.y, xa.z, xa.w, xb.x, xb.y, xb.z, xb.w};
        #pragma unroll
        for (int i = 0; i < 8; ++i) {
            acc[i][0] += xm[i] * w.x;
            acc[i][1] += xm[i] * w.y;
            acc[i][2] += xm[i] * w.z;
            acc[i][3] += xm[i] * w.w;
        }
    }

    bool isLin = (tn >= 8);
    int col = isLin ? (n0 - 32) : n0;
    float4 bw = isLin ? *reinterpret_cast<const float4*>(&sb2[col])
                      : make_float4(0.f, 0.f, 0.f, 0.f);
    float* dst = isLin ? lin : y;
    #pragma unroll
    for (int i = 0; i < 8; ++i) {
        int gn = base + m0 + i;
        if (gn < n) {
            float4 v = make_float4(acc[i][0] + bw.x, acc[i][1] + bw.y,
                                   acc[i][2] + bw.z, acc[i][3] + bw.w);
            *reinterpret_cast<float4*>(dst + (size_t)gn * D_H + col) = v;
        }
    }
}

// One thread per edge: gather full 128B src row (MLP=8), RED.128 x8 to dst row.
__global__ void k_scatter_edge(const int* __restrict__ edge, const float* __restrict__ feat,
                               float* __restrict__ agg, float* __restrict__ cnt, int E) {
    int e = blockIdx.x * blockDim.x + threadIdx.x;
    if (e >= E) return;
    int s = __ldg(&edge[e]);
    int d = __ldg(&edge[E + e]);
    const float4* src = reinterpret_cast<const float4*>(feat + (size_t)s * D_H);
    float4* dst = reinterpret_cast<float4*>(agg + (size_t)d * D_H);
    float4 v[8];
    #pragma unroll
    for (int q = 0; q < 8; ++q) v[q] = __ldg(src + q);
    #pragma unroll
    for (int q = 0; q < 8; ++q) atomicAdd(dst + q, v[q]);
    atomicAdd(cnt + d, 1.0f);
}

// Same, fused with layer-2 scalar scatter: aggs[d] += gsrc[s].
__global__ void k_scatter_edge_fused(const int* __restrict__ edge, const float* __restrict__ feat,
                                     float* __restrict__ agg, float* __restrict__ cnt,
                                     const float* __restrict__ gsrc, float* __restrict__ aggs,
                                     int E) {
    int e = blockIdx.x * blockDim.x + threadIdx.x;
    if (e >= E) return;
    int s = __ldg(&edge[e]);
    int d = __ldg(&edge[E + e]);
    const float4* src = reinterpret_cast<const float4*>(feat + (size_t)s * D_H);
    float4* dst = reinterpret_cast<float4*>(agg + (size_t)d * D_H);
    float gs = __ldg(gsrc + s);
    float4 v[8];
    #pragma unroll
    for (int q = 0; q < 8; ++q) v[q] = __ldg(src + q);
    #pragma unroll
    for (int q = 0; q < 8; ++q) atomicAdd(dst + q, v[q]);
    atomicAdd(cnt + d, 1.0f);
    atomicAdd(aggs + d, gs);
}

// Customer post: h = relu(agg/max(cnt,1) + lin); g = dot(h, weff). Warp/node.
__global__ void k_post_c(const float* __restrict__ agg, const float* __restrict__ cnt,
                         const float* __restrict__ lin, const float* __restrict__ weff,
                         float* __restrict__ g, int n) {
    int j = threadIdx.x & 31;
    int warpId = (blockIdx.x * blockDim.x + threadIdx.x) >> 5;
    int nWarps = (gridDim.x * blockDim.x) >> 5;
    float wj = weff[j];
    for (int node = warpId; node < n; node += nWarps) {
        float inv = 1.0f / fmaxf(cnt[node], 1.0f);
        float h = fmaxf(agg[(size_t)node * D_H + j] * inv + lin[(size_t)node * D_H + j], 0.f);
        float v = h * wj;
        #pragma unroll
        for (int o = 16; o; o >>= 1) v += __shfl_xor_sync(0xffffffffu, v, o);
        if (j == 0) g[node] = v;
    }
}

// Product post: + layer2 mean + sigmoid -> out.
__global__ void k_post_p(const float* __restrict__ agg, const float* __restrict__ cnt,
                         const float* __restrict__ lin, const float* __restrict__ weff,
                         const float* __restrict__ aggs, float* __restrict__ out, int n) {
    int j = threadIdx.x & 31;
    int warpId = (blockIdx.x * blockDim.x + threadIdx.x) >> 5;
    int nWarps = (gridDim.x * blockDim.x) >> 5;
    float wj = weff[j];
    float beff = g_bias_eff[0];
    for (int node = warpId; node < n; node += nWarps) {
        float inv = 1.0f / fmaxf(cnt[node], 1.0f);
        float h = fmaxf(agg[(size_t)node * D_H + j] * inv + lin[(size_t)node * D_H + j], 0.f);
        float v = h * wj;
        #pragma unroll
        for (int o = 16; o; o >>= 1) v += __shfl_xor_sync(0xffffffffu, v, o);
        if (j == 0) {
            float logit = aggs[node] * inv + v + beff;
            out[node] = 1.0f / (1.0f + expf(-logit));
        }
    }
}

// ---------------- launch ----------------------------------------------------

extern "C" void kernel_launch(void* const* d_in, const int* in_sizes, int n_in,
                              void* d_out, int out_size) {
    const float* x_customer = (const float*)d_in[0];
    const float* x_product  = (const float*)d_in[1];
    const int*   edge_c2p   = (const int*)d_in[2];
    const int*   edge_p2c   = (const int*)d_in[3];
    const float* W1l_r1 = (const float*)d_in[4];
    const float* b1_r1  = (const float*)d_in[5];
    const float* W1r_r1 = (const float*)d_in[6];
    const float* W1l_r2 = (const float*)d_in[7];
    const float* b1_r2  = (const float*)d_in[8];
    const float* W1r_r2 = (const float*)d_in[9];
    const float* W2l_r1 = (const float*)d_in[10];
    const float* b2_r1  = (const float*)d_in[11];
    const float* W2r_r1 = (const float*)d_in[12];
    const float* Wlin   = (const float*)d_in[16];
    const float* blin   = (const float*)d_in[17];
    float* out = (float*)d_out;

    const int N = N_NODES;
    const int E = in_sizes[2] / 2;

    float *p_aggp, *p_aggc, *p_ycp, *p_ypc, *p_linc, *p_linp;
    float *p_cntp, *p_cntc, *p_gc, *p_aggs, *p_w2l, *p_w2r;
    cudaGetSymbolAddress((void**)&p_aggp, g_aggp);
    cudaGetSymbolAddress((void**)&p_aggc, g_aggc);
    cudaGetSymbolAddress((void**)&p_ycp,  g_ycp);
    cudaGetSymbolAddress((void**)&p_ypc,  g_ypc);
    cudaGetSymbolAddress((void**)&p_linc, g_linc);
    cudaGetSymbolAddress((void**)&p_linp, g_linp);
    cudaGetSymbolAddress((void**)&p_cntp, g_cntp);
    cudaGetSymbolAddress((void**)&p_cntc, g_cntc);
    cudaGetSymbolAddress((void**)&p_gc,   g_gc);
    cudaGetSymbolAddress((void**)&p_aggs, g_aggs);
    cudaGetSymbolAddress((void**)&p_w2l,  g_w2l_eff);
    cudaGetSymbolAddress((void**)&p_w2r,  g_w2r_eff);

    const int TB = 256;
    const int GS_BLOCKS = 1480;
    int gemmBlocks = (N + BM - 1) / BM;
    int edgeBlocks = (E + TB - 1) / TB;

    // 0: zero all accumulators
    k_zero_all<<<1024, TB>>>();
    // 1: effective layer2 + head weights
    k_eff<<<1, 32>>>(W2l_r1, W2r_r1, b2_r1, Wlin, blin);
    // 2: product prep  (y_pc = x_p@W1l_r2, lin_p = x_p@W1r_r1 + b1_r1)
    k_prep<<<gemmBlocks, 256>>>(x_product, W1l_r2, W1r_r1, b1_r1, p_ypc, p_linp, N);
    // 3: customer prep (y_cp = x_c@W1l_r1, lin_c = x_c@W1r_r2 + b1_r2)
    k_prep<<<gemmBlocks, 256>>>(x_customer, W1l_r1, W1r_r2, b1_r2, p_ycp, p_linc, N);
    // 4: p2c scatter  <-- profiled launch
    k_scatter_edge<<<edgeBlocks, TB>>>(edge_p2c, p_ypc, p_aggc, p_cntc, E);
    // 5: customer post -> g_c
    k_post_c<<<GS_BLOCKS, TB>>>(p_aggc, p_cntc, p_linc, p_w2l, p_gc, N);
    // 6: c2p scatter fused with layer-2 scalar scatter
    k_scatter_edge_fused<<<edgeBlocks, TB>>>(edge_c2p, p_ycp, p_aggp, p_cntp, p_gc, p_aggs, E);
    // 7: product post + head + sigmoid
    k_post_p<<<GS_BLOCKS, TB>>>(p_aggp, p_cntp, p_linp, p_w2r, p_aggs, out, N);
}

// round 9
// speedup vs baseline: 1.4392x; 1.4392x over previous
#include <cuda_runtime.h>
#include <cuda_bf16.h>
#include <math.h>

#define N_NODES 100000
#define D_IN    64
#define D_H     32
#define TOTAL_H (N_NODES * D_H)
#define BM      128
#define XS      (BM + 4)

// ---------------- scratch (device globals, 16B aligned) ---------------------
__device__ __align__(16) float g_aggp[TOTAL_H];
__device__ __align__(16) float g_aggc[TOTAL_H];
__device__ __align__(16) float g_ycp [TOTAL_H];
__device__ __align__(16) float g_ypc [TOTAL_H];
__device__ __align__(16) float g_linc[TOTAL_H];
__device__ __align__(16) float g_linp[TOTAL_H];
__device__ __align__(16) float g_cntp[N_NODES];
__device__ __align__(16) float g_cntc[N_NODES];
__device__ __align__(16) float g_gc  [N_NODES];
__device__ __align__(16) float g_aggs[N_NODES];
__device__ float g_w2l_eff[D_H];
__device__ float g_w2r_eff[D_H];
__device__ float g_bias_eff[1];

// ---------------- kernels ---------------------------------------------------

__global__ void k_zero_all() {
    int i = blockIdx.x * blockDim.x + threadIdx.x;
    int stride = gridDim.x * blockDim.x;
    float4 z = make_float4(0.f, 0.f, 0.f, 0.f);
    for (int k = i; k < TOTAL_H / 4; k += stride) {
        reinterpret_cast<float4*>(g_aggp)[k] = z;
        reinterpret_cast<float4*>(g_aggc)[k] = z;
    }
    for (int k = i; k < N_NODES / 4; k += stride) {
        reinterpret_cast<float4*>(g_cntp)[k] = z;
        reinterpret_cast<float4*>(g_cntc)[k] = z;
        reinterpret_cast<float4*>(g_aggs)[k] = z;
    }
}

__global__ void k_eff(const float* __restrict__ W2l, const float* __restrict__ W2r,
                      const float* __restrict__ b2, const float* __restrict__ Wlin,
                      const float* __restrict__ blin) {
    int i = threadIdx.x;  // 0..31
    float wl = 0.f, wr = 0.f;
    #pragma unroll
    for (int j = 0; j < D_H; ++j) {
        float wj = Wlin[j];
        wl += W2l[i * D_H + j] * wj;
        wr += W2r[i * D_H + j] * wj;
    }
    g_w2l_eff[i] = wl;
    g_w2r_eff[i] = wr;
    float bv = b2[i] * Wlin[i];
    #pragma unroll
    for (int o = 16; o; o >>= 1) bv += __shfl_xor_sync(0xffffffffu, bv, o);
    if (i == 0) g_bias_eff[0] = bv + blin[0];
}

// Register-tiled GEMM: C[128 nodes][64 outs] = x_tile @ [Wl | Wr], K=64.
// cols 0..31 -> y, cols 32..63 -> lin (+bias).
// 256 threads; each computes 8 nodes x 4 outs. Per k: 3 LDS.128 + 32 FFMA.
__global__ void k_prep(const float* __restrict__ x,
                       const float* __restrict__ Wl, const float* __restrict__ Wr,
                       const float* __restrict__ b,
                       float* __restrict__ y, float* __restrict__ lin, int n) {
    __shared__ float sW[D_IN * 64];     // [k][out0..63] = [Wl | Wr]  (16KB)
    __shared__ float sX[D_IN * XS];     // [k][node], padded          (33.8KB)
    __shared__ float sb2[D_H];
    int tid = threadIdx.x;

    for (int i = tid; i < D_IN * 8; i += 256) {
        int k = i >> 3, q = i & 7;
        reinterpret_cast<float4*>(sW)[k * 16 + q]     = reinterpret_cast<const float4*>(Wl)[i];
        reinterpret_cast<float4*>(sW)[k * 16 + 8 + q] = reinterpret_cast<const float4*>(Wr)[i];
    }
    if (tid < D_H) sb2[tid] = b[tid];

    int base = blockIdx.x * BM;
    for (int i = tid; i < BM * 16; i += 256) {   // BM nodes * 16 float4
        int node = i >> 4;
        int q    = i & 15;
        int gn = base + node;
        float4 v = (gn < n) ? reinterpret_cast<const float4*>(x + (size_t)gn * D_IN)[q]
                            : make_float4(0.f, 0.f, 0.f, 0.f);
        int k4 = q * 4;
        sX[(k4 + 0) * XS + node] = v.x;
        sX[(k4 + 1) * XS + node] = v.y;
        sX[(k4 + 2) * XS + node] = v.z;
        sX[(k4 + 3) * XS + node] = v.w;
    }
    __syncthreads();

    int tn = tid & 15;        // output group: cols 4*tn .. 4*tn+3
    int tm = tid >> 4;        // node group:  rows 8*tm .. 8*tm+7 (0..15)
    int n0 = tn * 4, m0 = tm * 8;

    float acc[8][4];
    #pragma unroll
    for (int i = 0; i < 8; ++i)
        #pragma unroll
        for (int j = 0; j < 4; ++j) acc[i][j] = 0.f;

    #pragma unroll 4
    for (int k = 0; k < D_IN; ++k) {
        float4 w  = *reinterpret_cast<const float4*>(&sW[k * 64 + n0]);
        float4 xa = *reinterpret_cast<const float4*>(&sX[k * XS + m0]);
        float4 xb = *reinterpret_cast<const float4*>(&sX[k * XS + m0 + 4]);
        float xm[8] = {xa.x, xa.y, xa.z, xa.w, xb.x, xb.y, xb.z, xb.w};
        #pragma unroll
        for (int i = 0; i < 8; ++i) {
            acc[i][0] += xm[i] * w.x;
            acc[i][1] += xm[i] * w.y;
            acc[i][2] += xm[i] * w.z;
            acc[i][3] += xm[i] * w.w;
        }
    }

    bool isLin = (tn >= 8);
    int col = isLin ? (n0 - 32) : n0;
    float4 bw = isLin ? *reinterpret_cast<const float4*>(&sb2[col])
                      : make_float4(0.f, 0.f, 0.f, 0.f);
    float* dst = isLin ? lin : y;
    #pragma unroll
    for (int i = 0; i < 8; ++i) {
        int gn = base + m0 + i;
        if (gn < n) {
            float4 v = make_float4(acc[i][0] + bw.x, acc[i][1] + bw.y,
                                   acc[i][2] + bw.z, acc[i][3] + bw.w);
            *reinterpret_cast<float4*>(dst + (size_t)gn * D_H + col) = v;
        }
    }
}

// Per-edge scatter of 32-float rows + degree count. 8 threads/edge (float4).
// 8 lanes cover one contiguous 128B dst row -> coalesced RED wavefronts.
__global__ void k_scatter32(const int* __restrict__ edge, const float* __restrict__ feat,
                            float* __restrict__ agg, float* __restrict__ cnt, int E) {
    long long t = (long long)blockIdx.x * blockDim.x + threadIdx.x;
    int e    = (int)(t >> 3);
    int lane = (int)(t & 7);
    if (e >= E) return;
    int s = __ldg(&edge[e]);
    int d = __ldg(&edge[E + e]);
    float4 v = *reinterpret_cast<const float4*>(feat + (size_t)s * D_H + lane * 4);
    atomicAdd(reinterpret_cast<float4*>(agg + (size_t)d * D_H + lane * 4), v);
    if (lane == 0) atomicAdd(cnt + d, 1.0f);
}

// Same, fused with the layer-2 scalar scatter: aggs[d] += gsrc[s].
__global__ void k_scatter32_fused(const int* __restrict__ edge, const float* __restrict__ feat,
                                  float* __restrict__ agg, float* __restrict__ cnt,
                                  const float* __restrict__ gsrc, float* __restrict__ aggs,
                                  int E) {
    long long t = (long long)blockIdx.x * blockDim.x + threadIdx.x;
    int e    = (int)(t >> 3);
    int lane = (int)(t & 7);
    if (e >= E) return;
    int s = __ldg(&edge[e]);
    int d = __ldg(&edge[E + e]);
    float4 v = *reinterpret_cast<const float4*>(feat + (size_t)s * D_H + lane * 4);
    atomicAdd(reinterpret_cast<float4*>(agg + (size_t)d * D_H + lane * 4), v);
    if (lane == 0) atomicAdd(cnt + d, 1.0f);
    if (lane == 1) atomicAdd(aggs + d, __ldg(gsrc + s));
}

// Customer post: h = relu(agg/max(cnt,1) + lin); g = dot(h, weff). Warp/node.
__global__ void k_post_c(const float* __restrict__ agg, const float* __restrict__ cnt,
                         const float* __restrict__ lin, const float* __restrict__ weff,
                         float* __restrict__ g, int n) {
    int j = threadIdx.x & 31;
    int warpId = (blockIdx.x * blockDim.x + threadIdx.x) >> 5;
    int nWarps = (gridDim.x * blockDim.x) >> 5;
    float wj = weff[j];
    for (int node = warpId; node < n; node += nWarps) {
        float inv = 1.0f / fmaxf(cnt[node], 1.0f);
        float h = fmaxf(agg[(size_t)node * D_H + j] * inv + lin[(size_t)node * D_H + j], 0.f);
        float v = h * wj;
        #pragma unroll
        for (int o = 16; o; o >>= 1) v += __shfl_xor_sync(0xffffffffu, v, o);
        if (j == 0) g[node] = v;
    }
}

// Product post: + layer2 mean + sigmoid -> out.
__global__ void k_post_p(const float* __restrict__ agg, const float* __restrict__ cnt,
                         const float* __restrict__ lin, const float* __restrict__ weff,
                         const float* __restrict__ aggs, float* __restrict__ out, int n) {
    int j = threadIdx.x & 31;
    int warpId = (blockIdx.x * blockDim.x + threadIdx.x) >> 5;
    int nWarps = (gridDim.x * blockDim.x) >> 5;
    float wj = weff[j];
    float beff = g_bias_eff[0];
    for (int node = warpId; node < n; node += nWarps) {
        float inv = 1.0f / fmaxf(cnt[node], 1.0f);
        float h = fmaxf(agg[(size_t)node * D_H + j] * inv + lin[(size_t)node * D_H + j], 0.f);
        float v = h * wj;
        #pragma unroll
        for (int o = 16; o; o >>= 1) v += __shfl_xor_sync(0xffffffffu, v, o);
        if (j == 0) {
            float logit = aggs[node] * inv + v + beff;
            out[node] = 1.0f / (1.0f + expf(-logit));
        }
    }
}

// ---------------- launch ----------------------------------------------------

extern "C" void kernel_launch(void* const* d_in, const int* in_sizes, int n_in,
                              void* d_out, int out_size) {
    const float* x_customer = (const float*)d_in[0];
    const float* x_product  = (const float*)d_in[1];
    const int*   edge_c2p   = (const int*)d_in[2];
    const int*   edge_p2c   = (const int*)d_in[3];
    const float* W1l_r1 = (const float*)d_in[4];
    const float* b1_r1  = (const float*)d_in[5];
    const float* W1r_r1 = (const float*)d_in[6];
    const float* W1l_r2 = (const float*)d_in[7];
    const float* b1_r2  = (const float*)d_in[8];
    const float* W1r_r2 = (const float*)d_in[9];
    const float* W2l_r1 = (const float*)d_in[10];
    const float* b2_r1  = (const float*)d_in[11];
    const float* W2r_r1 = (const float*)d_in[12];
    const float* Wlin   = (const float*)d_in[16];
    const float* blin   = (const float*)d_in[17];
    float* out = (float*)d_out;

    const int N = N_NODES;
    const int E = in_sizes[2] / 2;

    float *p_aggp, *p_aggc, *p_ycp, *p_ypc, *p_linc, *p_linp;
    float *p_cntp, *p_cntc, *p_gc, *p_aggs, *p_w2l, *p_w2r;
    cudaGetSymbolAddress((void**)&p_aggp, g_aggp);
    cudaGetSymbolAddress((void**)&p_aggc, g_aggc);
    cudaGetSymbolAddress((void**)&p_ycp,  g_ycp);
    cudaGetSymbolAddress((void**)&p_ypc,  g_ypc);
    cudaGetSymbolAddress((void**)&p_linc, g_linc);
    cudaGetSymbolAddress((void**)&p_linp, g_linp);
    cudaGetSymbolAddress((void**)&p_cntp, g_cntp);
    cudaGetSymbolAddress((void**)&p_cntc, g_cntc);
    cudaGetSymbolAddress((void**)&p_gc,   g_gc);
    cudaGetSymbolAddress((void**)&p_aggs, g_aggs);
    cudaGetSymbolAddress((void**)&p_w2l,  g_w2l_eff);
    cudaGetSymbolAddress((void**)&p_w2r,  g_w2r_eff);

    const int TB = 256;
    const int GS_BLOCKS = 1480;
    int gemmBlocks = (N + BM - 1) / BM;

    long long scatThreads = (long long)E * 8;
    int scatBlocks = (int)((scatThreads + TB - 1) / TB);

    // 0: zero all accumulators
    k_zero_all<<<1024, TB>>>();
    // 1: effective layer2 + head weights
    k_eff<<<1, 32>>>(W2l_r1, W2r_r1, b2_r1, Wlin, blin);
    // 2: product prep  (y_pc = x_p@W1l_r2, lin_p = x_p@W1r_r1 + b1_r1)
    k_prep<<<gemmBlocks, 256>>>(x_product, W1l_r2, W1r_r1, b1_r1, p_ypc, p_linp, N);
    // 3: customer prep (y_cp = x_c@W1l_r1, lin_c = x_c@W1r_r2 + b1_r2)
    k_prep<<<gemmBlocks, 256>>>(x_customer, W1l_r1, W1r_r2, b1_r2, p_ycp, p_linc, N);
    // 4: p2c scatter
    k_scatter32<<<scatBlocks, TB>>>(edge_p2c, p_ypc, p_aggc, p_cntc, E);
    // 5: customer post -> g_c
    k_post_c<<<GS_BLOCKS, TB>>>(p_aggc, p_cntc, p_linc, p_w2l, p_gc, N);
    // 6: c2p scatter fused with layer-2 scalar scatter
    k_scatter32_fused<<<scatBlocks, TB>>>(edge_c2p, p_ycp, p_aggp, p_cntp, p_gc, p_aggs, E);
    // 7: product post + head + sigmoid
    k_post_p<<<GS_BLOCKS, TB>>>(p_aggp, p_cntp, p_linp, p_w2r, p_aggs, out, N);
}